// round 3
// baseline (speedup 1.0000x reference)
#include <cuda_runtime.h>

#define NQ   512
#define NK   1024
#define DIMC 256
#define NH   8
#define HD   32
#define RPE  512
#define NSEG (RPE + 1)

// ---------------- scratch (static __device__ — allocation-free) ----------------
static __device__ float          g_tsort[RPE];
static __device__ float          g_A[NH * NSEG];
static __device__ float          g_C[NH * NSEG];
static __device__ unsigned short g_seg[NQ * NK];
static __device__ float          g_q[NQ * DIMC];
static __device__ float          g_k[NK * DIMC];
static __device__ float          g_v[NK * DIMC];
static __device__ float          g_x[NQ * DIMC];

// =============================================================================
// Kernel 1: build piecewise-linear CPB bias tables (rank-sort, 2 syncs total).
// bias_h(m) = A[h][s]*m + C[h][s] where s = #breakpoints <= m.
// =============================================================================
__global__ void pwl_build(const float* __restrict__ W1, const float* __restrict__ b1,
                          const float* __restrict__ W2) {
    __shared__ float key[RPE];
    __shared__ float skey[RPE];
    __shared__ int   sidx[RPE];
    __shared__ float sW1[RPE], sb1[RPE];
    __shared__ float sW2[RPE * NH];

    const int tid = threadIdx.x;
    float w = W1[tid], b = b1[tid];
    float t;
    if (w != 0.0f) t = -b / w;
    else t = (b > 0.0f) ? -__int_as_float(0x7f800000) : __int_as_float(0x7f800000);
    key[tid] = t;
    sW1[tid] = w;
    sb1[tid] = b;
#pragma unroll
    for (int h = 0; h < NH; h++) sW2[tid * NH + h] = W2[tid * NH + h];
    __syncthreads();

    // rank sort: rank = #(keys < mine) + #(equal keys with smaller index)
    int rank = 0;
    float ki = t;
#pragma unroll 8
    for (int j = 0; j < RPE; j++) {
        float kj = key[j];
        rank += (kj < ki) || (kj == ki && j < tid);
    }
    skey[rank] = ki;
    sidx[rank] = tid;
    __syncthreads();
    g_tsort[tid] = skey[tid];

    // per-head warp scan (warps 0..7); lane handles 16 sorted positions
    const int warp = tid >> 5, lane = tid & 31;
    if (warp < NH) {
        const int h = warp;
        float eA[16], eC[16];
        float leA = 0.f, leC = 0.f, mA = 0.f, mC = 0.f;
#pragma unroll
        for (int pp = 0; pp < 16; pp++) {
            int p = lane * 16 + pp;
            int r = sidx[p];
            float w1 = sW1[r], bb = sb1[r], w2 = sW2[r * NH + h];
            float ca, cc; bool plus;
            if (w1 > 0.f)      { plus = true;  ca = w1 * w2; cc = bb * w2; }
            else if (w1 < 0.f) { plus = false; ca = w1 * w2; cc = bb * w2; }
            else               { plus = true;  ca = 0.f;     cc = (bb > 0.f) ? bb * w2 : 0.f; }
            float ea = plus ? ca : -ca;
            float ec = plus ? cc : -cc;
            eA[pp] = ea; eC[pp] = ec;
            leA += ea; leC += ec;
            if (!plus) { mA += ca; mC += cc; }
        }
        float inA = leA, inC = leC;
#pragma unroll
        for (int o = 1; o < 32; o <<= 1) {
            float ta = __shfl_up_sync(0xffffffffu, inA, o);
            float tc = __shfl_up_sync(0xffffffffu, inC, o);
            if (lane >= o) { inA += ta; inC += tc; }
        }
        float exA = inA - leA, exC = inC - leC;
#pragma unroll
        for (int o = 16; o > 0; o >>= 1) {
            mA += __shfl_xor_sync(0xffffffffu, mA, o);
            mC += __shfl_xor_sync(0xffffffffu, mC, o);
        }
        if (lane == 0) { g_A[h * NSEG] = mA; g_C[h * NSEG] = mC; }
        float runA = exA, runC = exC;
#pragma unroll
        for (int pp = 0; pp < 16; pp++) {
            runA += eA[pp]; runC += eC[pp];
            int s = lane * 16 + pp + 1;
            g_A[h * NSEG + s] = mA + runA;
            g_C[h * NSEG + s] = mC + runC;
        }
    }
}

// =============================================================================
// Kernel 2: segment index per (q,k) — head independent. 1 binary search each.
// =============================================================================
__global__ void seg_kernel(const float* __restrict__ am) {
    __shared__ float ts[RPE];
    int t = threadIdx.x;
    ts[t] = g_tsort[t];
    ts[t + 256] = g_tsort[t + 256];
    __syncthreads();
    int i = blockIdx.x * 256 + t;
    float m = am[i];
    int lo = 0, hi = RPE;
    while (lo < hi) {
        int mid = (lo + hi) >> 1;
        if (ts[mid] <= m) lo = mid + 1; else hi = mid;
    }
    g_seg[i] = (unsigned short)lo;
}

// =============================================================================
// Shared GEMM body: C[M,256] = (A[M,256] @ W[256,256] + bias) * scale
// 64x64 tile / block, 128 threads, 4x8 per thread, BK=16.  1.5B LDS per FMA.
// =============================================================================
__device__ __forceinline__ void gemm_body(const float* __restrict__ A, const float* __restrict__ W,
                                          const float* __restrict__ bias, float* __restrict__ C,
                                          int M, float scale) {
    __shared__ float As[16][68];
    __shared__ float Ws[16][72];
    int bm = blockIdx.y * 64;
    if (bm >= M) return;                     // uniform across block
    int bn = blockIdx.x * 64;
    int t = threadIdx.x;
    int ra = t >> 1, ka = (t & 1) * 8;       // A load: 2x float4 per thread
    int kw = t >> 3, nw = (t & 7) * 8;       // W load: 2x float4 per thread
    int ty = t >> 3, tx = t & 7;             // compute: rows ty*4.., cols tx*8..
    float acc[4][8] = {};
    for (int k0 = 0; k0 < DIMC; k0 += 16) {
        float4 a0 = *(const float4*)&A[(bm + ra) * DIMC + k0 + ka];
        float4 a1 = *(const float4*)&A[(bm + ra) * DIMC + k0 + ka + 4];
        float4 w0 = *(const float4*)&W[(k0 + kw) * DIMC + bn + nw];
        float4 w1 = *(const float4*)&W[(k0 + kw) * DIMC + bn + nw + 4];
        As[ka + 0][ra] = a0.x; As[ka + 1][ra] = a0.y; As[ka + 2][ra] = a0.z; As[ka + 3][ra] = a0.w;
        As[ka + 4][ra] = a1.x; As[ka + 5][ra] = a1.y; As[ka + 6][ra] = a1.z; As[ka + 7][ra] = a1.w;
        *(float4*)&Ws[kw][nw]     = w0;
        *(float4*)&Ws[kw][nw + 4] = w1;
        __syncthreads();
#pragma unroll
        for (int kk = 0; kk < 16; kk++) {
            float4 a4 = *(const float4*)&As[kk][ty * 4];
            float4 b0 = *(const float4*)&Ws[kk][tx * 8];
            float4 b1 = *(const float4*)&Ws[kk][tx * 8 + 4];
            float aa[4] = {a4.x, a4.y, a4.z, a4.w};
            float bb[8] = {b0.x, b0.y, b0.z, b0.w, b1.x, b1.y, b1.z, b1.w};
#pragma unroll
            for (int i = 0; i < 4; i++)
#pragma unroll
                for (int j = 0; j < 8; j++)
                    acc[i][j] += aa[i] * bb[j];
        }
        __syncthreads();
    }
    float4 bsa = *(const float4*)&bias[bn + tx * 8];
    float4 bsb = *(const float4*)&bias[bn + tx * 8 + 4];
    float bs[8] = {bsa.x, bsa.y, bsa.z, bsa.w, bsb.x, bsb.y, bsb.z, bsb.w};
#pragma unroll
    for (int i = 0; i < 4; i++) {
        int row = bm + ty * 4 + i;
        float4 o0, o1;
        o0.x = (acc[i][0] + bs[0]) * scale; o0.y = (acc[i][1] + bs[1]) * scale;
        o0.z = (acc[i][2] + bs[2]) * scale; o0.w = (acc[i][3] + bs[3]) * scale;
        o1.x = (acc[i][4] + bs[4]) * scale; o1.y = (acc[i][5] + bs[5]) * scale;
        o1.z = (acc[i][6] + bs[6]) * scale; o1.w = (acc[i][7] + bs[7]) * scale;
        *(float4*)&C[row * DIMC + bn + tx * 8]     = o0;
        *(float4*)&C[row * DIMC + bn + tx * 8 + 4] = o1;
    }
}

// Kernel 3: fused Q/K/V projections (blockIdx.z selects which)
__global__ void __launch_bounds__(128) gemm_qkv(
        const float* __restrict__ q_in, const float* __restrict__ k_in,
        const float* __restrict__ v_in,
        const float* __restrict__ Wq, const float* __restrict__ bq_,
        const float* __restrict__ Wk, const float* __restrict__ bk_,
        const float* __restrict__ Wv, const float* __restrict__ bv_) {
    const float *A, *W, *B; float *Cp; int M; float sc;
    if (blockIdx.z == 0)      { A = q_in; W = Wq; B = bq_; Cp = g_q; M = NQ; sc = 0.17677669529663687f; }
    else if (blockIdx.z == 1) { A = k_in; W = Wk; B = bk_; Cp = g_k; M = NK; sc = 1.0f; }
    else                      { A = v_in; W = Wv; B = bv_; Cp = g_v; M = NK; sc = 1.0f; }
    gemm_body(A, W, B, Cp, M, sc);
}

// Kernel 5: output projection
__global__ void __launch_bounds__(128) gemm_final(
        const float* __restrict__ Wp, const float* __restrict__ bp_,
        float* __restrict__ out) {
    gemm_body(g_x, Wp, bp_, out, NQ, 1.0f);
}

// =============================================================================
// Kernel 4: FUSED attention.  Block = (h, 32 q rows).  Grid (16, 8) = 128 blocks.
// Phase A: S[32][1024] in smem = QK^T + PWL-bias + pad   (K streamed, dbl-buf)
// Phase B: softmax in smem (exp stored unnormalized, 1/sum kept)
// Phase C: O = P @ V (V streamed, dbl-buf), scaled by 1/sum -> g_x
// smem ~181 KB -> 1 block/SM.
// All region offsets are multiples of 4 floats (16 B) — float4-safe.
// =============================================================================
#define TQ      32
#define SSTRIDE 1028                 // 1024 + 4 pad (bank-shifts rows by 4)
#define KSTRIDE 132                  // K tile [32 d][132]
#define VSTRIDE 36                   // V tile [128 k][36]
#define OFF_S   0
#define OFF_KV  (TQ * SSTRIDE)                   // 32896
#define OFF_Q   (OFF_KV + 2 * 128 * VSTRIDE)     // +9216
#define OFF_AC  (OFF_Q + 32 * 36)                // +1152
#define OFF_PAD (OFF_AC + 2 * NSEG + 2)          // +1028  (16B aligned!)
#define OFF_L   (OFF_PAD + NK)
#define SMEM_FLOATS (OFF_L + TQ)
#define SMEM_BYTES  (SMEM_FLOATS * 4)

__global__ void __launch_bounds__(256, 1) fused_attn(const float* __restrict__ am,
                                                     const float* __restrict__ pad) {
    extern __shared__ float sm[];
    float*  Ssm  = sm + OFF_S;
    float*  KV   = sm + OFF_KV;
    float*  Qs   = sm + OFF_Q;      // [d][q], stride 36
    float2* AC   = (float2*)(sm + OFF_AC);
    float*  padp = sm + OFF_PAD;
    float*  lsm  = sm + OFF_L;

    const int h    = blockIdx.y;
    const int bq   = blockIdx.x * TQ;
    const int t    = threadIdx.x;
    const int lane = t & 31, warp = t >> 5;

    // ---- prologue: Q tile (transposed), LUT, pad ----
    {
        int qr = t >> 3, d4 = (t & 7) * 4;
        float4 v = *(const float4*)&g_q[(bq + qr) * DIMC + h * HD + d4];
        Qs[(d4 + 0) * 36 + qr] = v.x; Qs[(d4 + 1) * 36 + qr] = v.y;
        Qs[(d4 + 2) * 36 + qr] = v.z; Qs[(d4 + 3) * 36 + qr] = v.w;
    }
    for (int i = t; i < NSEG; i += 256)
        AC[i] = make_float2(g_A[h * NSEG + i], g_C[h * NSEG + i]);
    {
        float4 p4 = *(const float4*)&pad[t * 4];
        float4 o; o.x = p4.x * -100.f; o.y = p4.y * -100.f; o.z = p4.z * -100.f; o.w = p4.w * -100.f;
        *(float4*)&padp[t * 4] = o;
    }

    // ---- Phase A: QK^T + bias, chunks of 128 k, double-buffered ----
    const int kk = t >> 1, db = (t & 1) * 16;       // load mapping (128 k x 32 d)
    float4 r0, r1, r2, r3;
    {
        const float* p = &g_k[kk * DIMC + h * HD + db];
        r0 = *(const float4*)p; r1 = *(const float4*)(p + 4);
        r2 = *(const float4*)(p + 8); r3 = *(const float4*)(p + 12);
        float* B = KV;                                  // buf 0, [d][132]
        B[(db + 0) * KSTRIDE + kk] = r0.x; B[(db + 1) * KSTRIDE + kk] = r0.y;
        B[(db + 2) * KSTRIDE + kk] = r0.z; B[(db + 3) * KSTRIDE + kk] = r0.w;
        B[(db + 4) * KSTRIDE + kk] = r1.x; B[(db + 5) * KSTRIDE + kk] = r1.y;
        B[(db + 6) * KSTRIDE + kk] = r1.z; B[(db + 7) * KSTRIDE + kk] = r1.w;
        B[(db + 8) * KSTRIDE + kk] = r2.x; B[(db + 9) * KSTRIDE + kk] = r2.y;
        B[(db +10) * KSTRIDE + kk] = r2.z; B[(db +11) * KSTRIDE + kk] = r2.w;
        B[(db +12) * KSTRIDE + kk] = r3.x; B[(db +13) * KSTRIDE + kk] = r3.y;
        B[(db +14) * KSTRIDE + kk] = r3.z; B[(db +15) * KSTRIDE + kk] = r3.w;
    }
    __syncthreads();
    const int rowb = warp * 4;                          // this warp's 4 q rows
    for (int c = 0; c < 8; c++) {
        if (c < 7) {
            const float* p = &g_k[((c + 1) * 128 + kk) * DIMC + h * HD + db];
            r0 = *(const float4*)p; r1 = *(const float4*)(p + 4);
            r2 = *(const float4*)(p + 8); r3 = *(const float4*)(p + 12);
        }
        const float* Kb = KV + (c & 1) * (32 * KSTRIDE);
        float acc[4][4] = {};
#pragma unroll
        for (int d = 0; d < HD; d++) {
            float4 qa = *(const float4*)&Qs[d * 36 + rowb];
            float4 kb = *(const float4*)&Kb[d * KSTRIDE + lane * 4];
            float aa[4] = {qa.x, qa.y, qa.z, qa.w};
            float bb[4] = {kb.x, kb.y, kb.z, kb.w};
#pragma unroll
            for (int i = 0; i < 4; i++)
#pragma unroll
                for (int j = 0; j < 4; j++)
                    acc[i][j] += aa[i] * bb[j];
        }
        int kcol = c * 128 + lane * 4;
#pragma unroll
        for (int i = 0; i < 4; i++) {
            int qg = bq + rowb + i;
            float4  m4 = *(const float4*)&am[qg * NK + kcol];
            ushort4 s4 = *(const ushort4*)&g_seg[qg * NK + kcol];
            float2 c0 = AC[s4.x], c1 = AC[s4.y], c2 = AC[s4.z], c3 = AC[s4.w];
            float4 o;
            o.x = acc[i][0] + fmaf(c0.x, m4.x, c0.y) + padp[kcol + 0];
            o.y = acc[i][1] + fmaf(c1.x, m4.y, c1.y) + padp[kcol + 1];
            o.z = acc[i][2] + fmaf(c2.x, m4.z, c2.y) + padp[kcol + 2];
            o.w = acc[i][3] + fmaf(c3.x, m4.w, c3.y) + padp[kcol + 3];
            *(float4*)&Ssm[(rowb + i) * SSTRIDE + kcol] = o;
        }
        if (c < 7) {
            float* B = KV + ((c + 1) & 1) * (32 * KSTRIDE);
            B[(db + 0) * KSTRIDE + kk] = r0.x; B[(db + 1) * KSTRIDE + kk] = r0.y;
            B[(db + 2) * KSTRIDE + kk] = r0.z; B[(db + 3) * KSTRIDE + kk] = r0.w;
            B[(db + 4) * KSTRIDE + kk] = r1.x; B[(db + 5) * KSTRIDE + kk] = r1.y;
            B[(db + 6) * KSTRIDE + kk] = r1.z; B[(db + 7) * KSTRIDE + kk] = r1.w;
            B[(db + 8) * KSTRIDE + kk] = r2.x; B[(db + 9) * KSTRIDE + kk] = r2.y;
            B[(db +10) * KSTRIDE + kk] = r2.z; B[(db +11) * KSTRIDE + kk] = r2.w;
            B[(db +12) * KSTRIDE + kk] = r3.x; B[(db +13) * KSTRIDE + kk] = r3.y;
            B[(db +14) * KSTRIDE + kk] = r3.z; B[(db +15) * KSTRIDE + kk] = r3.w;
        }
        __syncthreads();
    }

    // ---- Phase B: softmax (each warp: its 4 rows) ----
#pragma unroll
    for (int i = 0; i < 4; i++) {
        int r = rowb + i;
        float* Srow = &Ssm[r * SSTRIDE + lane * 4];
        float4 v[8];
        float mx = -3.0e38f;
#pragma unroll
        for (int j = 0; j < 8; j++) {
            v[j] = *(const float4*)&Srow[j * 128];
            mx = fmaxf(mx, fmaxf(fmaxf(v[j].x, v[j].y), fmaxf(v[j].z, v[j].w)));
        }
#pragma unroll
        for (int o = 16; o > 0; o >>= 1) mx = fmaxf(mx, __shfl_xor_sync(0xffffffffu, mx, o));
        float s = 0.f;
#pragma unroll
        for (int j = 0; j < 8; j++) {
            v[j].x = __expf(v[j].x - mx); v[j].y = __expf(v[j].y - mx);
            v[j].z = __expf(v[j].z - mx); v[j].w = __expf(v[j].w - mx);
            s += (v[j].x + v[j].y) + (v[j].z + v[j].w);
            *(float4*)&Srow[j * 128] = v[j];
        }
#pragma unroll
        for (int o = 16; o > 0; o >>= 1) s += __shfl_xor_sync(0xffffffffu, s, o);
        if (lane == 0) lsm[r] = 1.0f / s;
    }
    __syncthreads();

    // ---- Phase C: O = P @ V, chunks of 128 k, double-buffered ----
    {
        const float* p = &g_v[kk * DIMC + h * HD + db];
        r0 = *(const float4*)p; r1 = *(const float4*)(p + 4);
        r2 = *(const float4*)(p + 8); r3 = *(const float4*)(p + 12);
        float* B = KV + kk * VSTRIDE + db;
        *(float4*)(B) = r0; *(float4*)(B + 4) = r1;
        *(float4*)(B + 8) = r2; *(float4*)(B + 12) = r3;
    }
    __syncthreads();
    const int qr = t >> 3, d4 = (t & 7) * 4;
    float ox = 0.f, oy = 0.f, oz = 0.f, ow = 0.f;
    for (int c = 0; c < 8; c++) {
        if (c < 7) {
            const float* p = &g_v[((c + 1) * 128 + kk) * DIMC + h * HD + db];
            r0 = *(const float4*)p; r1 = *(const float4*)(p + 4);
            r2 = *(const float4*)(p + 8); r3 = *(const float4*)(p + 12);
        }
        const float* Vb = KV + (c & 1) * (128 * VSTRIDE);
        const float* Sr = &Ssm[qr * SSTRIDE + c * 128];
#pragma unroll 8
        for (int k = 0; k < 128; k += 4) {
            float4 p4 = *(const float4*)&Sr[k];
            float4 va = *(const float4*)&Vb[(k + 0) * VSTRIDE + d4];
            float4 vb = *(const float4*)&Vb[(k + 1) * VSTRIDE + d4];
            float4 vc = *(const float4*)&Vb[(k + 2) * VSTRIDE + d4];
            float4 vd = *(const float4*)&Vb[(k + 3) * VSTRIDE + d4];
            ox = fmaf(p4.x, va.x, ox); oy = fmaf(p4.x, va.y, oy);
            oz = fmaf(p4.x, va.z, oz); ow = fmaf(p4.x, va.w, ow);
            ox = fmaf(p4.y, vb.x, ox); oy = fmaf(p4.y, vb.y, oy);
            oz = fmaf(p4.y, vb.z, oz); ow = fmaf(p4.y, vb.w, ow);
            ox = fmaf(p4.z, vc.x, ox); oy = fmaf(p4.z, vc.y, oy);
            oz = fmaf(p4.z, vc.z, oz); ow = fmaf(p4.z, vc.w, ow);
            ox = fmaf(p4.w, vd.x, ox); oy = fmaf(p4.w, vd.y, oy);
            oz = fmaf(p4.w, vd.z, oz); ow = fmaf(p4.w, vd.w, ow);
        }
        if (c < 7) {
            float* B = KV + ((c + 1) & 1) * (128 * VSTRIDE) + kk * VSTRIDE + db;
            *(float4*)(B) = r0; *(float4*)(B + 4) = r1;
            *(float4*)(B + 8) = r2; *(float4*)(B + 12) = r3;
        }
        __syncthreads();
    }
    float inv = lsm[qr];
    float4 o; o.x = ox * inv; o.y = oy * inv; o.z = oz * inv; o.w = ow * inv;
    *(float4*)&g_x[(bq + qr) * DIMC + h * HD + d4] = o;
}

// =============================================================================
extern "C" void kernel_launch(void* const* d_in, const int* in_sizes, int n_in,
                              void* d_out, int out_size) {
    const float* query = (const float*)d_in[0];
    const float* kin   = (const float*)d_in[1];
    const float* vin   = (const float*)d_in[2];
    const float* pad   = (const float*)d_in[3];
    const float* am    = (const float*)d_in[4];
    const float* Wq    = (const float*)d_in[5];
    const float* bq    = (const float*)d_in[6];
    const float* Wk    = (const float*)d_in[7];
    const float* bk    = (const float*)d_in[8];
    const float* Wv    = (const float*)d_in[9];
    const float* bv    = (const float*)d_in[10];
    const float* Wp    = (const float*)d_in[11];
    const float* bp    = (const float*)d_in[12];
    const float* W1    = (const float*)d_in[13];
    const float* b1    = (const float*)d_in[14];
    const float* W2    = (const float*)d_in[15];
    float* out = (float*)d_out;

    cudaFuncSetAttribute(fused_attn, cudaFuncAttributeMaxDynamicSharedMemorySize, SMEM_BYTES);

    pwl_build<<<1, 512>>>(W1, b1, W2);
    seg_kernel<<<(NQ * NK) / 256, 256>>>(am);
    gemm_qkv<<<dim3(4, 16, 3), 128>>>(query, kin, vin, Wq, bq, Wk, bk, Wv, bv);
    fused_attn<<<dim3(16, 8), 256, SMEM_BYTES>>>(am, pad);
    gemm_final<<<dim3(4, 8), 128>>>(Wp, bp, out);
}

// round 4
// speedup vs baseline: 1.0553x; 1.0553x over previous
#include <cuda_runtime.h>

#define NQ   512
#define NK   1024
#define DIMC 256
#define NH   8
#define HD   32
#define RPE  512
#define NSEG (RPE + 1)

// ---------------- scratch (static __device__ — allocation-free) ----------------
static __device__ float          g_tsort[RPE];
static __device__ float          g_A[NH * NSEG];
static __device__ float          g_C[NH * NSEG];
static __device__ unsigned short g_seg[NQ * NK];
static __device__ float          g_q[NQ * DIMC];
static __device__ float          g_k[NK * DIMC];
static __device__ float          g_v[NK * DIMC];
static __device__ float          g_x[NQ * DIMC];

// =============================================================================
// Kernel 1: build piecewise-linear CPB bias tables (rank-sort, 2 syncs total).
// bias_h(m) = A[h][s]*m + C[h][s] where s = #breakpoints <= m.
// =============================================================================
__global__ void pwl_build(const float* __restrict__ W1, const float* __restrict__ b1,
                          const float* __restrict__ W2) {
    __shared__ float key[RPE];
    __shared__ float skey[RPE];
    __shared__ int   sidx[RPE];
    __shared__ float sW1[RPE], sb1[RPE];
    __shared__ float sW2[RPE * NH];

    const int tid = threadIdx.x;
    float w = W1[tid], b = b1[tid];
    float t;
    if (w != 0.0f) t = -b / w;
    else t = (b > 0.0f) ? -__int_as_float(0x7f800000) : __int_as_float(0x7f800000);
    key[tid] = t;
    sW1[tid] = w;
    sb1[tid] = b;
#pragma unroll
    for (int h = 0; h < NH; h++) sW2[tid * NH + h] = W2[tid * NH + h];
    __syncthreads();

    // rank sort (float4 compares): rank = #(keys < mine) + #(equal, smaller idx)
    int rank = 0;
    float ki = t;
#pragma unroll 4
    for (int j4 = 0; j4 < RPE / 4; j4++) {
        float4 kj = *(const float4*)&key[j4 * 4];
        int j = j4 * 4;
        rank += (kj.x < ki) || (kj.x == ki && (j + 0) < tid);
        rank += (kj.y < ki) || (kj.y == ki && (j + 1) < tid);
        rank += (kj.z < ki) || (kj.z == ki && (j + 2) < tid);
        rank += (kj.w < ki) || (kj.w == ki && (j + 3) < tid);
    }
    skey[rank] = ki;
    sidx[rank] = tid;
    __syncthreads();
    g_tsort[tid] = skey[tid];

    // per-head warp scan (warps 0..7); lane handles 16 sorted positions
    const int warp = tid >> 5, lane = tid & 31;
    if (warp < NH) {
        const int h = warp;
        float eA[16], eC[16];
        float leA = 0.f, leC = 0.f, mA = 0.f, mC = 0.f;
#pragma unroll
        for (int pp = 0; pp < 16; pp++) {
            int p = lane * 16 + pp;
            int r = sidx[p];
            float w1 = sW1[r], bb = sb1[r], w2 = sW2[r * NH + h];
            float ca, cc; bool plus;
            if (w1 > 0.f)      { plus = true;  ca = w1 * w2; cc = bb * w2; }
            else if (w1 < 0.f) { plus = false; ca = w1 * w2; cc = bb * w2; }
            else               { plus = true;  ca = 0.f;     cc = (bb > 0.f) ? bb * w2 : 0.f; }
            float ea = plus ? ca : -ca;
            float ec = plus ? cc : -cc;
            eA[pp] = ea; eC[pp] = ec;
            leA += ea; leC += ec;
            if (!plus) { mA += ca; mC += cc; }
        }
        float inA = leA, inC = leC;
#pragma unroll
        for (int o = 1; o < 32; o <<= 1) {
            float ta = __shfl_up_sync(0xffffffffu, inA, o);
            float tc = __shfl_up_sync(0xffffffffu, inC, o);
            if (lane >= o) { inA += ta; inC += tc; }
        }
        float exA = inA - leA, exC = inC - leC;
#pragma unroll
        for (int o = 16; o > 0; o >>= 1) {
            mA += __shfl_xor_sync(0xffffffffu, mA, o);
            mC += __shfl_xor_sync(0xffffffffu, mC, o);
        }
        if (lane == 0) { g_A[h * NSEG] = mA; g_C[h * NSEG] = mC; }
        float runA = exA, runC = exC;
#pragma unroll
        for (int pp = 0; pp < 16; pp++) {
            runA += eA[pp]; runC += eC[pp];
            int s = lane * 16 + pp + 1;
            g_A[h * NSEG + s] = mA + runA;
            g_C[h * NSEG + s] = mC + runC;
        }
    }
}

// =============================================================================
// Kernel 2: segment index per (q,k) — head independent. 1 binary search each.
// =============================================================================
__global__ void seg_kernel(const float* __restrict__ am) {
    __shared__ float ts[RPE];
    int t = threadIdx.x;
    ts[t] = g_tsort[t];
    ts[t + 256] = g_tsort[t + 256];
    __syncthreads();
    int i = blockIdx.x * 256 + t;
    float m = am[i];
    int lo = 0, hi = RPE;
    while (lo < hi) {
        int mid = (lo + hi) >> 1;
        if (ts[mid] <= m) lo = mid + 1; else hi = mid;
    }
    g_seg[i] = (unsigned short)lo;
}

// =============================================================================
// Shared GEMM body: C[M,256] = (A[M,256] @ W[256,256] + bias) * scale
// 64x64 tile / block, 128 threads, 4x8 per thread, BK=16.
// =============================================================================
__device__ __forceinline__ void gemm_body(const float* __restrict__ A, const float* __restrict__ W,
                                          const float* __restrict__ bias, float* __restrict__ C,
                                          int M, float scale) {
    __shared__ float As[16][68];
    __shared__ float Ws[16][72];
    int bm = blockIdx.y * 64;
    if (bm >= M) return;                     // uniform across block
    int bn = blockIdx.x * 64;
    int t = threadIdx.x;
    int ra = t >> 1, ka = (t & 1) * 8;
    int kw = t >> 3, nw = (t & 7) * 8;
    int ty = t >> 3, tx = t & 7;
    float acc[4][8] = {};
    for (int k0 = 0; k0 < DIMC; k0 += 16) {
        float4 a0 = *(const float4*)&A[(bm + ra) * DIMC + k0 + ka];
        float4 a1 = *(const float4*)&A[(bm + ra) * DIMC + k0 + ka + 4];
        float4 w0 = *(const float4*)&W[(k0 + kw) * DIMC + bn + nw];
        float4 w1 = *(const float4*)&W[(k0 + kw) * DIMC + bn + nw + 4];
        As[ka + 0][ra] = a0.x; As[ka + 1][ra] = a0.y; As[ka + 2][ra] = a0.z; As[ka + 3][ra] = a0.w;
        As[ka + 4][ra] = a1.x; As[ka + 5][ra] = a1.y; As[ka + 6][ra] = a1.z; As[ka + 7][ra] = a1.w;
        *(float4*)&Ws[kw][nw]     = w0;
        *(float4*)&Ws[kw][nw + 4] = w1;
        __syncthreads();
#pragma unroll
        for (int kk = 0; kk < 16; kk++) {
            float4 a4 = *(const float4*)&As[kk][ty * 4];
            float4 b0 = *(const float4*)&Ws[kk][tx * 8];
            float4 b1 = *(const float4*)&Ws[kk][tx * 8 + 4];
            float aa[4] = {a4.x, a4.y, a4.z, a4.w};
            float bb[8] = {b0.x, b0.y, b0.z, b0.w, b1.x, b1.y, b1.z, b1.w};
#pragma unroll
            for (int i = 0; i < 4; i++)
#pragma unroll
                for (int j = 0; j < 8; j++)
                    acc[i][j] += aa[i] * bb[j];
        }
        __syncthreads();
    }
    float4 bsa = *(const float4*)&bias[bn + tx * 8];
    float4 bsb = *(const float4*)&bias[bn + tx * 8 + 4];
    float bs[8] = {bsa.x, bsa.y, bsa.z, bsa.w, bsb.x, bsb.y, bsb.z, bsb.w};
#pragma unroll
    for (int i = 0; i < 4; i++) {
        int row = bm + ty * 4 + i;
        float4 o0, o1;
        o0.x = (acc[i][0] + bs[0]) * scale; o0.y = (acc[i][1] + bs[1]) * scale;
        o0.z = (acc[i][2] + bs[2]) * scale; o0.w = (acc[i][3] + bs[3]) * scale;
        o1.x = (acc[i][4] + bs[4]) * scale; o1.y = (acc[i][5] + bs[5]) * scale;
        o1.z = (acc[i][6] + bs[6]) * scale; o1.w = (acc[i][7] + bs[7]) * scale;
        *(float4*)&C[row * DIMC + bn + tx * 8]     = o0;
        *(float4*)&C[row * DIMC + bn + tx * 8 + 4] = o1;
    }
}

__global__ void __launch_bounds__(128) gemm_qkv(
        const float* __restrict__ q_in, const float* __restrict__ k_in,
        const float* __restrict__ v_in,
        const float* __restrict__ Wq, const float* __restrict__ bq_,
        const float* __restrict__ Wk, const float* __restrict__ bk_,
        const float* __restrict__ Wv, const float* __restrict__ bv_) {
    const float *A, *W, *B; float *Cp; int M; float sc;
    if (blockIdx.z == 0)      { A = q_in; W = Wq; B = bq_; Cp = g_q; M = NQ; sc = 0.17677669529663687f; }
    else if (blockIdx.z == 1) { A = k_in; W = Wk; B = bk_; Cp = g_k; M = NK; sc = 1.0f; }
    else                      { A = v_in; W = Wv; B = bv_; Cp = g_v; M = NK; sc = 1.0f; }
    gemm_body(A, W, B, Cp, M, sc);
}

__global__ void __launch_bounds__(128) gemm_final(
        const float* __restrict__ Wp, const float* __restrict__ bp_,
        float* __restrict__ out) {
    gemm_body(g_x, Wp, bp_, out, NQ, 1.0f);
}

// =============================================================================
// Kernel 4: FUSED attention, S stored TRANSPOSED: ST[k 1024][q 32], stride 36.
// Block = (h, 32 q rows).  Grid (16, 8), 256 threads, 1 block/SM (194KB smem).
// Phase A: QK^T + PWL-bias + pad -> ST (thread tile 4k x 4q, K streamed)
// Phase B: softmax columns of ST (warp per 128-k range, q = lane)
// Phase C: O = P^T' V outer product (thread tile 8q x 8d, 16 split-k groups)
// =============================================================================
#define TQ      32
#define STSTR   36
#define KSTR    132
#define VSTR    36
#define BUFSZ   4608
#define OFF_ST  0
#define OFF_KV  (NK * STSTR)              // 36864
#define OFF_Q   (OFF_KV + 2 * BUFSZ)      // 46080
#define OFF_AC  (OFF_Q + 32 * 36)         // 47232
#define OFF_PAD (OFF_AC + 2 * NSEG + 2)   // 48260 (16B aligned)
#define OFF_PM  (OFF_PAD + NK)            // 49284
#define OFF_PS  (OFF_PM + 256)
#define OFF_LI  (OFF_PS + 256)
#define SMEM_FLOATS (OFF_LI + 32)
#define SMEM_BYTES  (SMEM_FLOATS * 4)

__global__ void __launch_bounds__(256, 1) fused_attn(const float* __restrict__ am,
                                                     const float* __restrict__ pad) {
    extern __shared__ float sm[];
    float*  ST   = sm + OFF_ST;
    float*  KV   = sm + OFF_KV;
    float*  Qs   = sm + OFF_Q;      // [d][q], stride 36
    float2* AC   = (float2*)(sm + OFF_AC);
    float*  padp = sm + OFF_PAD;
    float*  pm   = sm + OFF_PM;
    float*  ps   = sm + OFF_PS;
    float*  linv = sm + OFF_LI;

    const int h    = blockIdx.y;
    const int bq   = blockIdx.x * TQ;
    const int t    = threadIdx.x;
    const int lane = t & 31, warp = t >> 5;

    // ---- prologue ----
    {
        int qr = t >> 3, d4 = (t & 7) * 4;
        float4 v = *(const float4*)&g_q[(bq + qr) * DIMC + h * HD + d4];
        Qs[(d4 + 0) * 36 + qr] = v.x; Qs[(d4 + 1) * 36 + qr] = v.y;
        Qs[(d4 + 2) * 36 + qr] = v.z; Qs[(d4 + 3) * 36 + qr] = v.w;
    }
    for (int i = t; i < NSEG; i += 256)
        AC[i] = make_float2(g_A[h * NSEG + i], g_C[h * NSEG + i]);
    {
        float4 p4 = *(const float4*)&pad[t * 4];
        float4 o; o.x = p4.x * -100.f; o.y = p4.y * -100.f; o.z = p4.z * -100.f; o.w = p4.w * -100.f;
        *(float4*)&padp[t * 4] = o;
    }

    // ---- Phase A ----
    const int kk = t >> 1, db = (t & 1) * 16;       // stream-load mapping
    float4 r0, r1, r2, r3;
    {
        const float* p = &g_k[kk * DIMC + h * HD + db];
        r0 = *(const float4*)p; r1 = *(const float4*)(p + 4);
        r2 = *(const float4*)(p + 8); r3 = *(const float4*)(p + 12);
        float* B = KV;
        B[(db + 0) * KSTR + kk] = r0.x; B[(db + 1) * KSTR + kk] = r0.y;
        B[(db + 2) * KSTR + kk] = r0.z; B[(db + 3) * KSTR + kk] = r0.w;
        B[(db + 4) * KSTR + kk] = r1.x; B[(db + 5) * KSTR + kk] = r1.y;
        B[(db + 6) * KSTR + kk] = r1.z; B[(db + 7) * KSTR + kk] = r1.w;
        B[(db + 8) * KSTR + kk] = r2.x; B[(db + 9) * KSTR + kk] = r2.y;
        B[(db +10) * KSTR + kk] = r2.z; B[(db +11) * KSTR + kk] = r2.w;
        B[(db +12) * KSTR + kk] = r3.x; B[(db +13) * KSTR + kk] = r3.y;
        B[(db +14) * KSTR + kk] = r3.z; B[(db +15) * KSTR + kk] = r3.w;
    }
    __syncthreads();
    const int tk4 = t >> 3;        // 0..31  (4 k each)
    const int tq4 = t & 7;         // 0..7   (4 q each)
    for (int c = 0; c < 8; c++) {
        if (c < 7) {
            const float* p = &g_k[((c + 1) * 128 + kk) * DIMC + h * HD + db];
            r0 = *(const float4*)p; r1 = *(const float4*)(p + 4);
            r2 = *(const float4*)(p + 8); r3 = *(const float4*)(p + 12);
        }
        const float* Kb = KV + (c & 1) * BUFSZ;
        float acc[4][4] = {};                       // [ki][qj]
#pragma unroll
        for (int d = 0; d < HD; d++) {
            float4 kb = *(const float4*)&Kb[d * KSTR + tk4 * 4];
            float4 qa = *(const float4*)&Qs[d * 36 + tq4 * 4];
            float kv[4] = {kb.x, kb.y, kb.z, kb.w};
            float qv[4] = {qa.x, qa.y, qa.z, qa.w};
#pragma unroll
            for (int i = 0; i < 4; i++)
#pragma unroll
                for (int j = 0; j < 4; j++)
                    acc[i][j] += kv[i] * qv[j];
        }
        const int kg0 = c * 128 + tk4 * 4;
#pragma unroll
        for (int j = 0; j < 4; j++) {
            int qg = bq + tq4 * 4 + j;
            float4  m4 = *(const float4*)&am[qg * NK + kg0];
            ushort4 s4 = *(const ushort4*)&g_seg[qg * NK + kg0];
            float2 c0 = AC[s4.x], c1 = AC[s4.y], c2 = AC[s4.z], c3 = AC[s4.w];
            acc[0][j] += fmaf(c0.x, m4.x, c0.y);
            acc[1][j] += fmaf(c1.x, m4.y, c1.y);
            acc[2][j] += fmaf(c2.x, m4.z, c2.y);
            acc[3][j] += fmaf(c3.x, m4.w, c3.y);
        }
#pragma unroll
        for (int i = 0; i < 4; i++) {
            float pdv = padp[kg0 + i];
            float4 o;
            o.x = acc[i][0] + pdv; o.y = acc[i][1] + pdv;
            o.z = acc[i][2] + pdv; o.w = acc[i][3] + pdv;
            *(float4*)&ST[(kg0 + i) * STSTR + tq4 * 4] = o;
        }
        if (c < 7) {
            float* B = KV + ((c + 1) & 1) * BUFSZ;
            B[(db + 0) * KSTR + kk] = r0.x; B[(db + 1) * KSTR + kk] = r0.y;
            B[(db + 2) * KSTR + kk] = r0.z; B[(db + 3) * KSTR + kk] = r0.w;
            B[(db + 4) * KSTR + kk] = r1.x; B[(db + 5) * KSTR + kk] = r1.y;
            B[(db + 6) * KSTR + kk] = r1.z; B[(db + 7) * KSTR + kk] = r1.w;
            B[(db + 8) * KSTR + kk] = r2.x; B[(db + 9) * KSTR + kk] = r2.y;
            B[(db +10) * KSTR + kk] = r2.z; B[(db +11) * KSTR + kk] = r2.w;
            B[(db +12) * KSTR + kk] = r3.x; B[(db +13) * KSTR + kk] = r3.y;
            B[(db +14) * KSTR + kk] = r3.z; B[(db +15) * KSTR + kk] = r3.w;
        }
        __syncthreads();
    }

    // ---- Phase B: softmax over k (columns of ST); warp w: k in [w*128, w*128+128), q = lane ----
    {
        const int kb = warp * 128;
        float mx = -3.0e38f;
#pragma unroll 4
        for (int i = 0; i < 128; i++)
            mx = fmaxf(mx, ST[(kb + i) * STSTR + lane]);
        pm[warp * 32 + lane] = mx;
        __syncthreads();
        float gm = pm[lane];
#pragma unroll
        for (int j = 1; j < 8; j++) gm = fmaxf(gm, pm[j * 32 + lane]);
        float s = 0.f;
#pragma unroll 4
        for (int i = 0; i < 128; i++) {
            int idx = (kb + i) * STSTR + lane;
            float e = __expf(ST[idx] - gm);
            ST[idx] = e;
            s += e;
        }
        ps[warp * 32 + lane] = s;
        __syncthreads();
        if (warp == 0) {
            float tot = ps[lane];
#pragma unroll
            for (int j = 1; j < 8; j++) tot += ps[j * 32 + lane];
            linv[lane] = 1.0f / tot;
        }
    }

    // ---- Phase C: O = P^T' V; thread = (g 0..15, tq8 0..3, td8 0..3), tile 8q x 8d ----
    {
        const float* p = &g_v[kk * DIMC + h * HD + db];
        r0 = *(const float4*)p; r1 = *(const float4*)(p + 4);
        r2 = *(const float4*)(p + 8); r3 = *(const float4*)(p + 12);
        float* B = KV + kk * VSTR + db;
        *(float4*)(B) = r0; *(float4*)(B + 4) = r1;
        *(float4*)(B + 8) = r2; *(float4*)(B + 12) = r3;
    }
    __syncthreads();

    const int g   = t >> 4;         // 0..15 split-k group
    const int tq8 = (t >> 2) & 3;   // q base = tq8*8
    const int td8 = t & 3;          // d base = td8*8
    float acc[8][8] = {};           // [qi][di]
    for (int c = 0; c < 8; c++) {
        if (c < 7) {
            const float* p = &g_v[((c + 1) * 128 + kk) * DIMC + h * HD + db];
            r0 = *(const float4*)p; r1 = *(const float4*)(p + 4);
            r2 = *(const float4*)(p + 8); r3 = *(const float4*)(p + 12);
        }
        const float* Vb = KV + (c & 1) * BUFSZ;
#pragma unroll
        for (int i = 0; i < 8; i++) {
            int kl = i * 16 + g;
            int kg = c * 128 + kl;
            float4 pA = *(const float4*)&ST[kg * STSTR + tq8 * 8];
            float4 pB = *(const float4*)&ST[kg * STSTR + tq8 * 8 + 4];
            float4 vA = *(const float4*)&Vb[kl * VSTR + td8 * 8];
            float4 vB = *(const float4*)&Vb[kl * VSTR + td8 * 8 + 4];
            float pq[8] = {pA.x, pA.y, pA.z, pA.w, pB.x, pB.y, pB.z, pB.w};
            float vd[8] = {vA.x, vA.y, vA.z, vA.w, vB.x, vB.y, vB.z, vB.w};
#pragma unroll
            for (int qi = 0; qi < 8; qi++)
#pragma unroll
                for (int di = 0; di < 8; di++)
                    acc[qi][di] += pq[qi] * vd[di];
        }
        if (c < 7) {
            float* B = KV + ((c + 1) & 1) * BUFSZ + kk * VSTR + db;
            *(float4*)(B) = r0; *(float4*)(B + 4) = r1;
            *(float4*)(B + 8) = r2; *(float4*)(B + 12) = r3;
        }
        __syncthreads();
    }

    // split-k reduce: level 1 via shfl_xor(16) (g bit 0 lives in lane bit 4)
#pragma unroll
    for (int qi = 0; qi < 8; qi++)
#pragma unroll
        for (int di = 0; di < 8; di++)
            acc[qi][di] += __shfl_xor_sync(0xffffffffu, acc[qi][di], 16);

    // stage 8 slabs (threads with lane bit4==0), reuse ST region
    float* red = ST;
    if ((t & 16) == 0) {
        int g1 = g >> 1;            // 0..7
#pragma unroll
        for (int qi = 0; qi < 8; qi++) {
            int q = tq8 * 8 + qi;
            float4 a; a.x = acc[qi][0]; a.y = acc[qi][1]; a.z = acc[qi][2]; a.w = acc[qi][3];
            float4 b; b.x = acc[qi][4]; b.y = acc[qi][5]; b.z = acc[qi][6]; b.w = acc[qi][7];
            *(float4*)&red[g1 * 1024 + q * 32 + td8 * 8]     = a;
            *(float4*)&red[g1 * 1024 + q * 32 + td8 * 8 + 4] = b;
        }
    }
    __syncthreads();

    // final: thread handles output float4 at o = t*4  (q = t>>3, d = (t&7)*4)
    {
        float4 s = *(const float4*)&red[t * 4];
#pragma unroll
        for (int j = 1; j < 8; j++) {
            float4 v = *(const float4*)&red[j * 1024 + t * 4];
            s.x += v.x; s.y += v.y; s.z += v.z; s.w += v.w;
        }
        float inv = linv[t >> 3];
        s.x *= inv; s.y *= inv; s.z *= inv; s.w *= inv;
        *(float4*)&g_x[(bq + (t >> 3)) * DIMC + h * HD + (t & 7) * 4] = s;
    }
}

// =============================================================================
extern "C" void kernel_launch(void* const* d_in, const int* in_sizes, int n_in,
                              void* d_out, int out_size) {
    const float* query = (const float*)d_in[0];
    const float* kin   = (const float*)d_in[1];
    const float* vin   = (const float*)d_in[2];
    const float* pad   = (const float*)d_in[3];
    const float* am    = (const float*)d_in[4];
    const float* Wq    = (const float*)d_in[5];
    const float* bq    = (const float*)d_in[6];
    const float* Wk    = (const float*)d_in[7];
    const float* bk    = (const float*)d_in[8];
    const float* Wv    = (const float*)d_in[9];
    const float* bv    = (const float*)d_in[10];
    const float* Wp    = (const float*)d_in[11];
    const float* bp    = (const float*)d_in[12];
    const float* W1    = (const float*)d_in[13];
    const float* b1    = (const float*)d_in[14];
    const float* W2    = (const float*)d_in[15];
    float* out = (float*)d_out;

    cudaFuncSetAttribute(fused_attn, cudaFuncAttributeMaxDynamicSharedMemorySize, SMEM_BYTES);

    pwl_build<<<1, 512>>>(W1, b1, W2);
    seg_kernel<<<(NQ * NK) / 256, 256>>>(am);
    gemm_qkv<<<dim3(4, 16, 3), 128>>>(query, kin, vin, Wq, bq, Wk, bk, Wv, bv);
    fused_attn<<<dim3(16, 8), 256, SMEM_BYTES>>>(am, pad);
    gemm_final<<<dim3(4, 8), 128>>>(Wp, bp, out);
}